// round 13
// baseline (speedup 1.0000x reference)
#include <cuda_runtime.h>
#include <cuda_bf16.h>
#include <cstdint>

// Problem constants
#define BB 16
#define CC 64
#define NN 2048
#define KK 20
#define OUTC 64
#define EPS 1e-5f
#define NEG_SLOPE 0.2f

// ---------------- scratch (device globals; no allocation allowed) ----------
__device__ float g_xt[BB * NN * CC];            // (b, n, c)   8 MB
__device__ float g_sq[BB * NN];                 // 128 KB
__device__ float g_dist[BB * NN * NN];          // 268 MB
__device__ int   g_idx[BB * NN * KK];           // 2.6 MB
__device__ float g_y[BB * OUTC * NN];           // 8 MB
__device__ float g_wc[(KK + 1) * CC * OUTC];    // [j][c][o], j=20 is combined central slice
__device__ float g_scale[OUTC];
__device__ float g_shift[OUTC];

// ---------------- 1) transpose x (B,C,N) -> xt (B,N,C) --------------------
__global__ void transpose_k(const float* __restrict__ x) {
    __shared__ float tile[32][33];
    int b = blockIdx.z;
    int n0 = blockIdx.x * 32;
    int c0 = blockIdx.y * 32;
    int tx = threadIdx.x, ty = threadIdx.y;   // (32, 8)
#pragma unroll
    for (int u = 0; u < 4; ++u) {
        int c = c0 + ty + u * 8;
        tile[ty + u * 8][tx] = x[(size_t)b * CC * NN + (size_t)c * NN + n0 + tx];
    }
    __syncthreads();
#pragma unroll
    for (int u = 0; u < 4; ++u) {
        int n = n0 + ty + u * 8;
        g_xt[(size_t)b * NN * CC + (size_t)n * CC + c0 + tx] = tile[tx][ty + u * 8];
    }
}

// ---------------- 2) squared norms per point --------------------------------
// XLA:CPU EmitVectorizedReduce (ShardedVector) emulation, NEON 4-wide x2:
// 8 lane accumulators s_m = sum over c ≡ m (mod 8) (separate rn mul/add,
// c ascending); shard combine by VECTOR add: t_l = s_l + s_{l+4};
// then SEQUENTIAL scalar fold of the 4 lanes: ((t0 + t1) + t2) + t3.
__global__ void sq_k() {
    int row = blockIdx.x * 256 + threadIdx.x;     // < B*N
    if (row >= BB * NN) return;
    const float4* p = (const float4*)(g_xt + (size_t)row * CC);
    float s0 = 0.f, s1 = 0.f, s2 = 0.f, s3 = 0.f;
    float s4 = 0.f, s5 = 0.f, s6 = 0.f, s7 = 0.f;
#pragma unroll
    for (int u = 0; u < 8; ++u) {
        float4 a = p[2 * u];
        float4 b = p[2 * u + 1];
        s0 = __fadd_rn(s0, __fmul_rn(a.x, a.x));
        s1 = __fadd_rn(s1, __fmul_rn(a.y, a.y));
        s2 = __fadd_rn(s2, __fmul_rn(a.z, a.z));
        s3 = __fadd_rn(s3, __fmul_rn(a.w, a.w));
        s4 = __fadd_rn(s4, __fmul_rn(b.x, b.x));
        s5 = __fadd_rn(s5, __fmul_rn(b.y, b.y));
        s6 = __fadd_rn(s6, __fmul_rn(b.z, b.z));
        s7 = __fadd_rn(s7, __fmul_rn(b.w, b.w));
    }
    float t0 = __fadd_rn(s0, s4);
    float t1 = __fadd_rn(s1, s5);
    float t2 = __fadd_rn(s2, s6);
    float t3 = __fadd_rn(s3, s7);
    // sequential scalar fold (NOT balanced pairing)
    g_sq[row] = __fadd_rn(__fadd_rn(__fadd_rn(t0, t1), t2), t3);
}

// ---------------- 3) weight precombine --------------------------------------
// g_wc[j][c][o]:  j<20 -> w[o, C+c, j] ; j==20 -> sum_j (w[o,c,j] - w[o,C+c,j])
__global__ void wcomb_k(const float* __restrict__ w) {
    int id = blockIdx.x * 256 + threadIdx.x;
    if (id >= (KK + 1) * CC * OUTC) return;
    int j = id >> 12;          // / 4096
    int c = (id >> 6) & 63;
    int o = id & 63;
    float v;
    if (j < KK) {
        v = w[o * (2 * CC * KK) + (CC + c) * KK + j];
    } else {
        v = 0.f;
        for (int jj = 0; jj < KK; ++jj)
            v += w[o * (2 * CC * KK) + c * KK + jj]
               - w[o * (2 * CC * KK) + (CC + c) * KK + jj];
    }
    g_wc[id] = v;
}

// ---------------- 4) distance GEMM: dist = sq_i + sq_j - 2 * xt xt^T --------
// 128x128 tile per block, 256 threads, 8x8 micro-tile, K = C = 64.
// Inner product: single fp32 accumulator, FFMA, c ascending (Eigen gebp:
// per-output-element sequential fmla chain — best-measured config).
__global__ __launch_bounds__(256) void dist_k() {
    extern __shared__ float sm[];
    float (*As)[68]  = (float(*)[68])sm;                  // [128][68] (i, c)
    float (*Bs)[132] = (float(*)[132])(sm + 128 * 68);    // [64][132] (c, j)

    int b = blockIdx.z;
    int i0 = blockIdx.y * 128;
    int j0 = blockIdx.x * 128;
    int t = threadIdx.x;
    const float* xb = g_xt + (size_t)b * NN * CC;

    {
        int row = t >> 1;
        int half = (t & 1) * 32;
        const float4* sa = (const float4*)(xb + (size_t)(i0 + row) * CC + half);
        const float4* sb = (const float4*)(xb + (size_t)(j0 + row) * CC + half);
#pragma unroll
        for (int u = 0; u < 8; ++u) {
            float4 v = sa[u];
            *(float4*)&As[row][half + 4 * u] = v;
        }
#pragma unroll
        for (int u = 0; u < 8; ++u) {
            float4 v = sb[u];
            int c = half + 4 * u;
            Bs[c][row] = v.x; Bs[c + 1][row] = v.y;
            Bs[c + 2][row] = v.z; Bs[c + 3][row] = v.w;
        }
    }
    __syncthreads();

    int tx = t & 15, ty = t >> 4;
    float acc[8][8];
#pragma unroll
    for (int r = 0; r < 8; ++r)
#pragma unroll
        for (int s = 0; s < 8; ++s) acc[r][s] = 0.f;

#pragma unroll 8
    for (int c = 0; c < 64; ++c) {
        float4 b0 = *(const float4*)&Bs[c][tx * 8];
        float4 b1 = *(const float4*)&Bs[c][tx * 8 + 4];
        float bv[8] = {b0.x, b0.y, b0.z, b0.w, b1.x, b1.y, b1.z, b1.w};
        float av[8];
#pragma unroll
        for (int r = 0; r < 8; ++r) av[r] = As[ty * 8 + r][c];
#pragma unroll
        for (int r = 0; r < 8; ++r)
#pragma unroll
            for (int s = 0; s < 8; ++s)
                acc[r][s] = __fmaf_rn(av[r], bv[s], acc[r][s]);
    }

    float sqi[8], sqj[8];
#pragma unroll
    for (int r = 0; r < 8; ++r) sqi[r] = g_sq[b * NN + i0 + ty * 8 + r];
#pragma unroll
    for (int s = 0; s < 8; ++s) sqj[s] = g_sq[b * NN + j0 + tx * 8 + s];

#pragma unroll
    for (int r = 0; r < 8; ++r) {
        float* dr = g_dist + ((size_t)b * NN + i0 + ty * 8 + r) * NN + j0 + tx * 8;
        float4 o0, o1;
        // (sq_i + sq_j) - 2*dot, each step rounded separately (2*dot exact)
        o0.x = __fsub_rn(__fadd_rn(sqi[r], sqj[0]), 2.f * acc[r][0]);
        o0.y = __fsub_rn(__fadd_rn(sqi[r], sqj[1]), 2.f * acc[r][1]);
        o0.z = __fsub_rn(__fadd_rn(sqi[r], sqj[2]), 2.f * acc[r][2]);
        o0.w = __fsub_rn(__fadd_rn(sqi[r], sqj[3]), 2.f * acc[r][3]);
        o1.x = __fsub_rn(__fadd_rn(sqi[r], sqj[4]), 2.f * acc[r][4]);
        o1.y = __fsub_rn(__fadd_rn(sqi[r], sqj[5]), 2.f * acc[r][5]);
        o1.z = __fsub_rn(__fadd_rn(sqi[r], sqj[6]), 2.f * acc[r][6]);
        o1.w = __fsub_rn(__fadd_rn(sqi[r], sqj[7]), 2.f * acc[r][7]);
        *(float4*)dr = o0;
        *(float4*)(dr + 4) = o1;
    }
}

// ---------------- 5) top-20 nearest (excluding self), ascending, tie->lower idx
__global__ __launch_bounds__(256) void topk_k() {
    int row = blockIdx.x;                 // b*N + i
    int i = row & (NN - 1);
    int t = threadIdx.x;
    int lane = t & 31, warp = t >> 5;
    const float* d = g_dist + (size_t)row * NN;

    unsigned long long key[8];
#pragma unroll
    for (int q = 0; q < 8; ++q) {
        int j = t + 256 * q;
        float f = d[j];
        unsigned long long k =
            ((unsigned long long)__float_as_uint(f) << 32) | (unsigned)j;
        key[q] = (j == i) ? 0xFFFFFFFFFFFFFFFFull : k;
    }

    __shared__ unsigned long long wmin[8];
    __shared__ unsigned long long sbcast;

    for (int r = 0; r < KK; ++r) {
        unsigned long long m = key[0];
#pragma unroll
        for (int q = 1; q < 8; ++q) m = (key[q] < m) ? key[q] : m;
#pragma unroll
        for (int off = 16; off; off >>= 1) {
            unsigned long long o = __shfl_down_sync(0xFFFFFFFFu, m, off);
            m = (o < m) ? o : m;
        }
        if (lane == 0) wmin[warp] = m;
        __syncthreads();
        if (t == 0) {
            unsigned long long g = wmin[0];
#pragma unroll
            for (int wq = 1; wq < 8; ++wq) g = (wmin[wq] < g) ? wmin[wq] : g;
            sbcast = g;
            g_idx[row * KK + r] = (int)(g & 0xFFFFFFFFull);
        }
        __syncthreads();
        unsigned long long g = sbcast;
#pragma unroll
        for (int q = 0; q < 8; ++q)
            if (key[q] == g) key[q] = 0xFFFFFFFFFFFFFFFFull;
    }
}

// ---------------- 6) edge conv:  y[b,o,n] ------------------------------------
// Block: (n-tile of 64 points) x (all 64 outputs). 256 threads, 4o x 4p micro.
__global__ __launch_bounds__(256) void conv_k(const float* __restrict__ bias) {
    __shared__ float As[64][68];   // [p][c] gathered features
    __shared__ float Ws[64][64];   // [c][o]

    int n0 = blockIdx.x * 64;
    int b = blockIdx.y;
    int t = threadIdx.x;
    int o4 = t & 15;      // output group (4 outs)
    int p4 = t >> 4;      // point group (4 points)
    int lp = t >> 2;      // gather: point
    int lq = t & 3;       // gather: quarter of the 64-ch row

    float acc[4][4];
#pragma unroll
    for (int pp = 0; pp < 4; ++pp)
#pragma unroll
        for (int oo = 0; oo < 4; ++oo)
            acc[pp][oo] = bias[o4 * 4 + oo];

    for (int j = 0; j <= KK; ++j) {
        // weights slice [c][o]
        const float4* wsrc = (const float4*)(g_wc + j * CC * OUTC);
#pragma unroll
        for (int u = 0; u < 4; ++u)
            ((float4*)&Ws[0][0])[t + 256 * u] = wsrc[t + 256 * u];

        // gather features: j<20 -> neighbor, j==20 -> central point
        int g = (j < KK) ? g_idx[((b << 11) + n0 + lp) * KK + j] : (n0 + lp);
        const float4* src =
            (const float4*)(g_xt + ((size_t)(b << 11) + g) * CC) + lq * 4;
#pragma unroll
        for (int u = 0; u < 4; ++u) {
            float4 v = src[u];
            *(float4*)&As[lp][lq * 16 + u * 4] = v;
        }
        __syncthreads();

#pragma unroll 8
        for (int c = 0; c < 64; ++c) {
            float4 w4 = *(const float4*)&Ws[c][o4 * 4];
            float wv[4] = {w4.x, w4.y, w4.z, w4.w};
#pragma unroll
            for (int pp = 0; pp < 4; ++pp) {
                float a = As[p4 * 4 + pp][c];
#pragma unroll
                for (int oo = 0; oo < 4; ++oo)
                    acc[pp][oo] += a * wv[oo];
            }
        }
        __syncthreads();
    }

#pragma unroll
    for (int pp = 0; pp < 4; ++pp)
#pragma unroll
        for (int oo = 0; oo < 4; ++oo)
            g_y[(size_t)b * OUTC * NN + (o4 * 4 + oo) * NN + n0 + p4 * 4 + pp] =
                acc[pp][oo];
}

// ---------------- 7) BN stats per output channel -----------------------------
__global__ void stats_k(const float* __restrict__ gamma,
                        const float* __restrict__ beta) {
    int o = blockIdx.x;
    int t = threadIdx.x;
    float s = 0.f, ss = 0.f;
    for (int b = 0; b < BB; ++b) {
        const float* p = g_y + (size_t)b * OUTC * NN + (size_t)o * NN;
        for (int n = t; n < NN; n += 256) {
            float v = p[n];
            s += v;
            ss += v * v;
        }
    }
    __shared__ float rs[256], rs2[256];
    rs[t] = s; rs2[t] = ss;
    __syncthreads();
    for (int off = 128; off; off >>= 1) {
        if (t < off) { rs[t] += rs[t + off]; rs2[t] += rs2[t + off]; }
        __syncthreads();
    }
    if (t == 0) {
        float inv = 1.f / (float)(BB * NN);
        float mean = rs[0] * inv;
        float var = rs2[0] * inv - mean * mean;
        if (var < 0.f) var = 0.f;
        float sc = gamma[o] * rsqrtf(var + EPS);
        g_scale[o] = sc;
        g_shift[o] = beta[o] - mean * sc;
    }
}

// ---------------- 8) normalize + leaky relu ----------------------------------
__global__ void final_k(float* __restrict__ out) {
    int i4 = blockIdx.x * 256 + threadIdx.x;   // float4 index
    int e = i4 * 4;
    int o = (e >> 11) & 63;
    float sc = g_scale[o], sh = g_shift[o];
    float4 v = ((const float4*)g_y)[i4];
    float4 r;
    r.x = v.x * sc + sh; r.x = (r.x >= 0.f) ? r.x : NEG_SLOPE * r.x;
    r.y = v.y * sc + sh; r.y = (r.y >= 0.f) ? r.y : NEG_SLOPE * r.y;
    r.z = v.z * sc + sh; r.z = (r.z >= 0.f) ? r.z : NEG_SLOPE * r.z;
    r.w = v.w * sc + sh; r.w = (r.w >= 0.f) ? r.w : NEG_SLOPE * r.w;
    ((float4*)out)[i4] = r;
}

// ---------------- launch -----------------------------------------------------
extern "C" void kernel_launch(void* const* d_in, const int* in_sizes, int n_in,
                              void* d_out, int out_size) {
    const float* x     = (const float*)d_in[0];
    const float* w     = (const float*)d_in[1];
    const float* bias  = (const float*)d_in[2];
    const float* gamma = (const float*)d_in[3];
    const float* beta  = (const float*)d_in[4];
    float* out = (float*)d_out;

    transpose_k<<<dim3(NN / 32, CC / 32, BB), dim3(32, 8)>>>(x);
    sq_k<<<(BB * NN + 255) / 256, 256>>>();
    wcomb_k<<<((KK + 1) * CC * OUTC + 255) / 256, 256>>>(w);

    const int dist_smem = (128 * 68 + 64 * 132) * sizeof(float);  // 68608 B
    cudaFuncSetAttribute(dist_k, cudaFuncAttributeMaxDynamicSharedMemorySize,
                         dist_smem);
    dist_k<<<dim3(NN / 128, NN / 128, BB), 256, dist_smem>>>();

    topk_k<<<BB * NN, 256>>>();
    conv_k<<<dim3(NN / 64, BB), 256>>>(bias);
    stats_k<<<OUTC, 256>>>(gamma, beta);
    final_k<<<(BB * OUTC * NN) / (4 * 256), 256>>>(out);
}

// round 14
// speedup vs baseline: 1.0608x; 1.0608x over previous
#include <cuda_runtime.h>
#include <cuda_bf16.h>
#include <cstdint>

// Problem constants
#define BB 16
#define CC 64
#define NN 2048
#define KK 20
#define OUTC 64
#define EPS 1e-5f
#define NEG_SLOPE 0.2f

// ---------------- scratch (device globals; no allocation allowed) ----------
__device__ float g_xt[BB * NN * CC];            // (b, n, c)   8 MB
__device__ float g_sq[BB * NN];                 // 128 KB
__device__ float g_dist[BB * NN * NN];          // 268 MB
__device__ int   g_idx[BB * NN * KK];           // 2.6 MB
__device__ float g_y[BB * OUTC * NN];           // 8 MB
__device__ float g_wc[(KK + 1) * CC * OUTC];    // [j][c][o], j=20 is combined central slice
__device__ float g_scale[OUTC];
__device__ float g_shift[OUTC];

// ---------------- 1) transpose x (B,C,N) -> xt (B,N,C) --------------------
__global__ void transpose_k(const float* __restrict__ x) {
    __shared__ float tile[32][33];
    int b = blockIdx.z;
    int n0 = blockIdx.x * 32;
    int c0 = blockIdx.y * 32;
    int tx = threadIdx.x, ty = threadIdx.y;   // (32, 8)
#pragma unroll
    for (int u = 0; u < 4; ++u) {
        int c = c0 + ty + u * 8;
        tile[ty + u * 8][tx] = x[(size_t)b * CC * NN + (size_t)c * NN + n0 + tx];
    }
    __syncthreads();
#pragma unroll
    for (int u = 0; u < 4; ++u) {
        int n = n0 + ty + u * 8;
        g_xt[(size_t)b * NN * CC + (size_t)n * CC + c0 + tx] = tile[tx][ty + u * 8];
    }
}

// ---------------- 2) squared norms per point --------------------------------
// FROZEN (matches reference bit-exactly — R13 PASS):
// 8 lane accumulators s_m (c ≡ m mod 8, separate rn mul/add, c ascending);
// shard combine t_l = s_l + s_{l+4}; sequential fold ((t0+t1)+t2)+t3.
__global__ void sq_k() {
    int row = blockIdx.x * 256 + threadIdx.x;     // < B*N
    if (row >= BB * NN) return;
    const float4* p = (const float4*)(g_xt + (size_t)row * CC);
    float s0 = 0.f, s1 = 0.f, s2 = 0.f, s3 = 0.f;
    float s4 = 0.f, s5 = 0.f, s6 = 0.f, s7 = 0.f;
#pragma unroll
    for (int u = 0; u < 8; ++u) {
        float4 a = p[2 * u];
        float4 b = p[2 * u + 1];
        s0 = __fadd_rn(s0, __fmul_rn(a.x, a.x));
        s1 = __fadd_rn(s1, __fmul_rn(a.y, a.y));
        s2 = __fadd_rn(s2, __fmul_rn(a.z, a.z));
        s3 = __fadd_rn(s3, __fmul_rn(a.w, a.w));
        s4 = __fadd_rn(s4, __fmul_rn(b.x, b.x));
        s5 = __fadd_rn(s5, __fmul_rn(b.y, b.y));
        s6 = __fadd_rn(s6, __fmul_rn(b.z, b.z));
        s7 = __fadd_rn(s7, __fmul_rn(b.w, b.w));
    }
    float t0 = __fadd_rn(s0, s4);
    float t1 = __fadd_rn(s1, s5);
    float t2 = __fadd_rn(s2, s6);
    float t3 = __fadd_rn(s3, s7);
    g_sq[row] = __fadd_rn(__fadd_rn(__fadd_rn(t0, t1), t2), t3);
}

// ---------------- 3) weight precombine --------------------------------------
__global__ void wcomb_k(const float* __restrict__ w) {
    int id = blockIdx.x * 256 + threadIdx.x;
    if (id >= (KK + 1) * CC * OUTC) return;
    int j = id >> 12;          // / 4096
    int c = (id >> 6) & 63;
    int o = id & 63;
    float v;
    if (j < KK) {
        v = w[o * (2 * CC * KK) + (CC + c) * KK + j];
    } else {
        v = 0.f;
        for (int jj = 0; jj < KK; ++jj)
            v += w[o * (2 * CC * KK) + c * KK + jj]
               - w[o * (2 * CC * KK) + (CC + c) * KK + jj];
    }
    g_wc[id] = v;
}

// ---------------- 4) distance GEMM, UPPER-TRIANGLE TILES + MIRROR -----------
// dist(i,j) == dist(j,i) BIT-EXACTLY: fma(a,b,acc)==fma(b,a,acc) and
// __fadd_rn(sqi,sqj) is commutative. Compute 136 tiles (j0>=i0), mirror
// off-diagonal tiles via an smem transpose with coalesced stores.
// Dot: single fp32 accumulator, FFMA, c ascending — FROZEN numerics.
__global__ __launch_bounds__(256) void dist_k() {
    extern __shared__ float sm[];
    float (*As)[132] = (float(*)[132])sm;                 // [64][132] (c, i-pt)
    float (*Bs)[132] = (float(*)[132])(sm + 64 * 132);    // [64][132] (c, j-pt)
    float (*Ts)[129] = (float(*)[129])sm;                 // overlay: [128][129]

    int b = blockIdx.z;
    // decode upper-triangle tile index -> (ti, tj), tj >= ti
    int xidx = blockIdx.x;
    int ti = 0;
    while (xidx >= 16 - ti) { xidx -= 16 - ti; ++ti; }
    int tj = ti + xidx;
    int i0 = ti * 128;
    int j0 = tj * 128;

    int t = threadIdx.x;
    const float* xb = g_xt + (size_t)b * NN * CC;

    {
        int row = t >> 1;
        int half = (t & 1) * 32;
        const float4* sa = (const float4*)(xb + (size_t)(i0 + row) * CC + half);
        const float4* sb = (const float4*)(xb + (size_t)(j0 + row) * CC + half);
#pragma unroll
        for (int u = 0; u < 8; ++u) {
            float4 v = sa[u];
            int c = half + 4 * u;
            As[c][row] = v.x; As[c + 1][row] = v.y;
            As[c + 2][row] = v.z; As[c + 3][row] = v.w;
        }
#pragma unroll
        for (int u = 0; u < 8; ++u) {
            float4 v = sb[u];
            int c = half + 4 * u;
            Bs[c][row] = v.x; Bs[c + 1][row] = v.y;
            Bs[c + 2][row] = v.z; Bs[c + 3][row] = v.w;
        }
    }
    __syncthreads();

    int tx = t & 15, ty = t >> 4;
    float acc[8][8];
#pragma unroll
    for (int r = 0; r < 8; ++r)
#pragma unroll
        for (int s = 0; s < 8; ++s) acc[r][s] = 0.f;

#pragma unroll 8
    for (int c = 0; c < 64; ++c) {
        float4 a0 = *(const float4*)&As[c][ty * 8];
        float4 a1 = *(const float4*)&As[c][ty * 8 + 4];
        float4 b0 = *(const float4*)&Bs[c][tx * 8];
        float4 b1 = *(const float4*)&Bs[c][tx * 8 + 4];
        float av[8] = {a0.x, a0.y, a0.z, a0.w, a1.x, a1.y, a1.z, a1.w};
        float bv[8] = {b0.x, b0.y, b0.z, b0.w, b1.x, b1.y, b1.z, b1.w};
#pragma unroll
        for (int r = 0; r < 8; ++r)
#pragma unroll
            for (int s = 0; s < 8; ++s)
                acc[r][s] = __fmaf_rn(av[r], bv[s], acc[r][s]);
    }

    float sqi[8], sqj[8];
#pragma unroll
    for (int r = 0; r < 8; ++r) sqi[r] = g_sq[b * NN + i0 + ty * 8 + r];
#pragma unroll
    for (int s = 0; s < 8; ++s) sqj[s] = g_sq[b * NN + j0 + tx * 8 + s];

    // combine in place (exact same op sequence as R13), then write normal tile
#pragma unroll
    for (int r = 0; r < 8; ++r) {
#pragma unroll
        for (int s = 0; s < 8; ++s)
            acc[r][s] = __fsub_rn(__fadd_rn(sqi[r], sqj[s]), 2.f * acc[r][s]);
        float* dr = g_dist + ((size_t)b * NN + i0 + ty * 8 + r) * NN + j0 + tx * 8;
        float4 o0, o1;
        o0.x = acc[r][0]; o0.y = acc[r][1]; o0.z = acc[r][2]; o0.w = acc[r][3];
        o1.x = acc[r][4]; o1.y = acc[r][5]; o1.z = acc[r][6]; o1.w = acc[r][7];
        *(float4*)dr = o0;
        *(float4*)(dr + 4) = o1;
    }

    if (ti == tj) return;

    // mirror: stage transposed tile in smem, then coalesced store to (j0, i0)
    __syncthreads();            // all reads of As/Bs done before overlay write
#pragma unroll
    for (int r = 0; r < 8; ++r)
#pragma unroll
        for (int s = 0; s < 8; ++s)
            Ts[tx * 8 + s][ty * 8 + r] = acc[r][s];
    __syncthreads();
    {
        int row2 = t >> 1;              // 0..127 (row of mirrored tile)
        int half2 = (t & 1) * 64;       // each thread: 64 floats
        float* dr = g_dist + ((size_t)b * NN + j0 + row2) * NN + i0 + half2;
#pragma unroll
        for (int u = 0; u < 16; ++u) {
            int k = half2 + 4 * u;
            float4 w;
            w.x = Ts[row2][k];     w.y = Ts[row2][k + 1];
            w.z = Ts[row2][k + 2]; w.w = Ts[row2][k + 3];
            *(float4*)(dr + 4 * u) = w;
        }
    }
}

// ---------------- 5) top-20 nearest: warp-local top-20 -> merge --------------
// Same selection semantics as R13 (repeated extraction of the global min over
// UNIQUE u64 (dist,idx) keys — reduction order irrelevant). 1 barrier total.
__global__ __launch_bounds__(256) void topk_k() {
    int row = blockIdx.x;                 // b*N + i
    int i = row & (NN - 1);
    int t = threadIdx.x;
    int lane = t & 31, warp = t >> 5;
    const float* d = g_dist + (size_t)row * NN;

    unsigned long long key[8];
#pragma unroll
    for (int q = 0; q < 8; ++q) {
        int j = t + 256 * q;
        float f = d[j];
        unsigned long long k =
            ((unsigned long long)__float_as_uint(f) << 32) | (unsigned)j;
        key[q] = (j == i) ? 0xFFFFFFFFFFFFFFFFull : k;
    }

    __shared__ unsigned long long cand[8][KK];

    // Phase 1: each warp extracts its own top-20 (no block barriers)
    for (int r = 0; r < KK; ++r) {
        unsigned long long m = key[0];
#pragma unroll
        for (int q = 1; q < 8; ++q) m = (key[q] < m) ? key[q] : m;
#pragma unroll
        for (int off = 16; off; off >>= 1) {
            unsigned long long o = __shfl_down_sync(0xFFFFFFFFu, m, off);
            m = (o < m) ? o : m;
        }
        m = __shfl_sync(0xFFFFFFFFu, m, 0);     // broadcast winner
        if (lane == 0) cand[warp][r] = m;
#pragma unroll
        for (int q = 0; q < 8; ++q)
            if (key[q] == m) key[q] = 0xFFFFFFFFFFFFFFFFull;
    }
    __syncthreads();

    // Phase 2: warp 0 merges the 160 candidates (global top-20 is a subset)
    if (warp == 0) {
        unsigned long long k2[5];
#pragma unroll
        for (int v = 0; v < 5; ++v) {
            int idx = lane + v * 32;            // < 160
            k2[v] = cand[idx / KK][idx % KK];
        }
        for (int r = 0; r < KK; ++r) {
            unsigned long long m = k2[0];
#pragma unroll
            for (int v = 1; v < 5; ++v) m = (k2[v] < m) ? k2[v] : m;
#pragma unroll
            for (int off = 16; off; off >>= 1) {
                unsigned long long o = __shfl_down_sync(0xFFFFFFFFu, m, off);
                m = (o < m) ? o : m;
            }
            m = __shfl_sync(0xFFFFFFFFu, m, 0);
            if (lane == 0) g_idx[row * KK + r] = (int)(m & 0xFFFFFFFFull);
#pragma unroll
            for (int v = 0; v < 5; ++v)
                if (k2[v] == m) k2[v] = 0xFFFFFFFFFFFFFFFFull;
        }
    }
}

// ---------------- 6) edge conv:  y[b,o,n] ------------------------------------
__global__ __launch_bounds__(256) void conv_k(const float* __restrict__ bias) {
    __shared__ float As[64][68];   // [p][c] gathered features
    __shared__ float Ws[64][64];   // [c][o]

    int n0 = blockIdx.x * 64;
    int b = blockIdx.y;
    int t = threadIdx.x;
    int o4 = t & 15;      // output group (4 outs)
    int p4 = t >> 4;      // point group (4 points)
    int lp = t >> 2;      // gather: point
    int lq = t & 3;       // gather: quarter of the 64-ch row

    float acc[4][4];
#pragma unroll
    for (int pp = 0; pp < 4; ++pp)
#pragma unroll
        for (int oo = 0; oo < 4; ++oo)
            acc[pp][oo] = bias[o4 * 4 + oo];

    for (int j = 0; j <= KK; ++j) {
        const float4* wsrc = (const float4*)(g_wc + j * CC * OUTC);
#pragma unroll
        for (int u = 0; u < 4; ++u)
            ((float4*)&Ws[0][0])[t + 256 * u] = wsrc[t + 256 * u];

        int g = (j < KK) ? g_idx[((b << 11) + n0 + lp) * KK + j] : (n0 + lp);
        const float4* src =
            (const float4*)(g_xt + ((size_t)(b << 11) + g) * CC) + lq * 4;
#pragma unroll
        for (int u = 0; u < 4; ++u) {
            float4 v = src[u];
            *(float4*)&As[lp][lq * 16 + u * 4] = v;
        }
        __syncthreads();

#pragma unroll 8
        for (int c = 0; c < 64; ++c) {
            float4 w4 = *(const float4*)&Ws[c][o4 * 4];
            float wv[4] = {w4.x, w4.y, w4.z, w4.w};
#pragma unroll
            for (int pp = 0; pp < 4; ++pp) {
                float a = As[p4 * 4 + pp][c];
#pragma unroll
                for (int oo = 0; oo < 4; ++oo)
                    acc[pp][oo] += a * wv[oo];
            }
        }
        __syncthreads();
    }

#pragma unroll
    for (int pp = 0; pp < 4; ++pp)
#pragma unroll
        for (int oo = 0; oo < 4; ++oo)
            g_y[(size_t)b * OUTC * NN + (o4 * 4 + oo) * NN + n0 + p4 * 4 + pp] =
                acc[pp][oo];
}

// ---------------- 7) BN stats per output channel -----------------------------
__global__ void stats_k(const float* __restrict__ gamma,
                        const float* __restrict__ beta) {
    int o = blockIdx.x;
    int t = threadIdx.x;
    float s = 0.f, ss = 0.f;
    for (int b = 0; b < BB; ++b) {
        const float* p = g_y + (size_t)b * OUTC * NN + (size_t)o * NN;
        for (int n = t; n < NN; n += 256) {
            float v = p[n];
            s += v;
            ss += v * v;
        }
    }
    __shared__ float rs[256], rs2[256];
    rs[t] = s; rs2[t] = ss;
    __syncthreads();
    for (int off = 128; off; off >>= 1) {
        if (t < off) { rs[t] += rs[t + off]; rs2[t] += rs2[t + off]; }
        __syncthreads();
    }
    if (t == 0) {
        float inv = 1.f / (float)(BB * NN);
        float mean = rs[0] * inv;
        float var = rs2[0] * inv - mean * mean;
        if (var < 0.f) var = 0.f;
        float sc = gamma[o] * rsqrtf(var + EPS);
        g_scale[o] = sc;
        g_shift[o] = beta[o] - mean * sc;
    }
}

// ---------------- 8) normalize + leaky relu ----------------------------------
__global__ void final_k(float* __restrict__ out) {
    int i4 = blockIdx.x * 256 + threadIdx.x;   // float4 index
    int e = i4 * 4;
    int o = (e >> 11) & 63;
    float sc = g_scale[o], sh = g_shift[o];
    float4 v = ((const float4*)g_y)[i4];
    float4 r;
    r.x = v.x * sc + sh; r.x = (r.x >= 0.f) ? r.x : NEG_SLOPE * r.x;
    r.y = v.y * sc + sh; r.y = (r.y >= 0.f) ? r.y : NEG_SLOPE * r.y;
    r.z = v.z * sc + sh; r.z = (r.z >= 0.f) ? r.z : NEG_SLOPE * r.z;
    r.w = v.w * sc + sh; r.w = (r.w >= 0.f) ? r.w : NEG_SLOPE * r.w;
    ((float4*)out)[i4] = r;
}

// ---------------- launch -----------------------------------------------------
extern "C" void kernel_launch(void* const* d_in, const int* in_sizes, int n_in,
                              void* d_out, int out_size) {
    const float* x     = (const float*)d_in[0];
    const float* w     = (const float*)d_in[1];
    const float* bias  = (const float*)d_in[2];
    const float* gamma = (const float*)d_in[3];
    const float* beta  = (const float*)d_in[4];
    float* out = (float*)d_out;

    transpose_k<<<dim3(NN / 32, CC / 32, BB), dim3(32, 8)>>>(x);
    sq_k<<<(BB * NN + 255) / 256, 256>>>();
    wcomb_k<<<((KK + 1) * CC * OUTC + 255) / 256, 256>>>(w);

    const int dist_smem = 2 * 64 * 132 * sizeof(float);   // 67584 B (Ts overlays)
    cudaFuncSetAttribute(dist_k, cudaFuncAttributeMaxDynamicSharedMemorySize,
                         dist_smem);
    dist_k<<<dim3(136, 1, BB), 256, dist_smem>>>();

    topk_k<<<BB * NN, 256>>>();
    conv_k<<<dim3(NN / 64, BB), 256>>>(bias);
    stats_k<<<OUTC, 256>>>(gamma, beta);
    final_k<<<(BB * OUTC * NN) / (4 * 256), 256>>>(out);
}

// round 16
// speedup vs baseline: 1.4249x; 1.3432x over previous
#include <cuda_runtime.h>
#include <cuda_bf16.h>
#include <cstdint>

// Problem constants
#define BB 16
#define CC 64
#define NN 2048
#define KK 20
#define OUTC 64
#define EPS 1e-5f
#define NEG_SLOPE 0.2f

#define F32_INF __int_as_float(0x7f800000)

// packed f32x2 helpers (per-lane rn; FFMA2 ≡ 2x scalar FFMA bitwise)
#define PK2(out, lo, hi) \
    asm("mov.b64 %0, {%1, %2};" : "=l"(out) : "f"(lo), "f"(hi))
#define UPK2(lo, hi, in) \
    asm("mov.b64 {%0, %1}, %2;" : "=f"(lo), "=f"(hi) : "l"(in))
#define FMA2(acc, a2, b2) \
    asm("fma.rn.f32x2 %0, %1, %2, %0;" : "+l"(acc) : "l"(a2), "l"(b2))

// ---------------- scratch (device globals; no allocation allowed) ----------
__device__ float g_xt[BB * NN * CC];            // (b, n, c)   8 MB
__device__ float g_sq[BB * NN];                 // 128 KB
__device__ float g_dist[BB * NN * NN];          // 268 MB
__device__ int   g_idx[BB * NN * KK];           // 2.6 MB
__device__ float g_y[BB * OUTC * NN];           // 8 MB
__device__ float g_wc[(KK + 1) * CC * OUTC];    // [j][c][o], j=20 central slice
__device__ float g_scale[OUTC];
__device__ float g_shift[OUTC];

// ---------------- 1) transpose x (B,C,N) -> xt (B,N,C) --------------------
__global__ void transpose_k(const float* __restrict__ x) {
    __shared__ float tile[32][33];
    int b = blockIdx.z;
    int n0 = blockIdx.x * 32;
    int c0 = blockIdx.y * 32;
    int tx = threadIdx.x, ty = threadIdx.y;   // (32, 8)
#pragma unroll
    for (int u = 0; u < 4; ++u) {
        int c = c0 + ty + u * 8;
        tile[ty + u * 8][tx] = x[(size_t)b * CC * NN + (size_t)c * NN + n0 + tx];
    }
    __syncthreads();
#pragma unroll
    for (int u = 0; u < 4; ++u) {
        int n = n0 + ty + u * 8;
        g_xt[(size_t)b * NN * CC + (size_t)n * CC + c0 + tx] = tile[tx][ty + u * 8];
    }
}

// ---------------- 2) squared norms per point --------------------------------
// FROZEN (bit-exact vs reference — R13 PASS): mod-8 lanes, separate rn
// mul/add, shard add t_l = s_l+s_{l+4}, sequential fold ((t0+t1)+t2)+t3.
__global__ void sq_k() {
    int row = blockIdx.x * 256 + threadIdx.x;     // < B*N
    if (row >= BB * NN) return;
    const float4* p = (const float4*)(g_xt + (size_t)row * CC);
    float s0 = 0.f, s1 = 0.f, s2 = 0.f, s3 = 0.f;
    float s4 = 0.f, s5 = 0.f, s6 = 0.f, s7 = 0.f;
#pragma unroll
    for (int u = 0; u < 8; ++u) {
        float4 a = p[2 * u];
        float4 b = p[2 * u + 1];
        s0 = __fadd_rn(s0, __fmul_rn(a.x, a.x));
        s1 = __fadd_rn(s1, __fmul_rn(a.y, a.y));
        s2 = __fadd_rn(s2, __fmul_rn(a.z, a.z));
        s3 = __fadd_rn(s3, __fmul_rn(a.w, a.w));
        s4 = __fadd_rn(s4, __fmul_rn(b.x, b.x));
        s5 = __fadd_rn(s5, __fmul_rn(b.y, b.y));
        s6 = __fadd_rn(s6, __fmul_rn(b.z, b.z));
        s7 = __fadd_rn(s7, __fmul_rn(b.w, b.w));
    }
    float t0 = __fadd_rn(s0, s4);
    float t1 = __fadd_rn(s1, s5);
    float t2 = __fadd_rn(s2, s6);
    float t3 = __fadd_rn(s3, s7);
    g_sq[row] = __fadd_rn(__fadd_rn(__fadd_rn(t0, t1), t2), t3);
}

// ---------------- 3) weight precombine --------------------------------------
__global__ void wcomb_k(const float* __restrict__ w) {
    int id = blockIdx.x * 256 + threadIdx.x;
    if (id >= (KK + 1) * CC * OUTC) return;
    int j = id >> 12;
    int c = (id >> 6) & 63;
    int o = id & 63;
    float v;
    if (j < KK) {
        v = w[o * (2 * CC * KK) + (CC + c) * KK + j];
    } else {
        v = 0.f;
        for (int jj = 0; jj < KK; ++jj)
            v += w[o * (2 * CC * KK) + c * KK + jj]
               - w[o * (2 * CC * KK) + (CC + c) * KK + jj];
    }
    g_wc[id] = v;
}

// ---------------- 4) distance GEMM, upper-triangle + mirror (FROZEN numerics)
__global__ __launch_bounds__(256) void dist_k() {
    extern __shared__ float sm[];
    float (*As)[132] = (float(*)[132])sm;                 // [64][132] (c, i-pt)
    float (*Bs)[132] = (float(*)[132])(sm + 64 * 132);    // [64][132] (c, j-pt)
    float (*Ts)[129] = (float(*)[129])sm;                 // overlay: [128][129]

    int b = blockIdx.z;
    int xidx = blockIdx.x;
    int ti = 0;
    while (xidx >= 16 - ti) { xidx -= 16 - ti; ++ti; }
    int tj = ti + xidx;
    int i0 = ti * 128;
    int j0 = tj * 128;

    int t = threadIdx.x;
    const float* xb = g_xt + (size_t)b * NN * CC;

    {
        int row = t >> 1;
        int half = (t & 1) * 32;
        const float4* sa = (const float4*)(xb + (size_t)(i0 + row) * CC + half);
        const float4* sb = (const float4*)(xb + (size_t)(j0 + row) * CC + half);
#pragma unroll
        for (int u = 0; u < 8; ++u) {
            float4 v = sa[u];
            int c = half + 4 * u;
            As[c][row] = v.x; As[c + 1][row] = v.y;
            As[c + 2][row] = v.z; As[c + 3][row] = v.w;
        }
#pragma unroll
        for (int u = 0; u < 8; ++u) {
            float4 v = sb[u];
            int c = half + 4 * u;
            Bs[c][row] = v.x; Bs[c + 1][row] = v.y;
            Bs[c + 2][row] = v.z; Bs[c + 3][row] = v.w;
        }
    }
    __syncthreads();

    int tx = t & 15, ty = t >> 4;
    float acc[8][8];
#pragma unroll
    for (int r = 0; r < 8; ++r)
#pragma unroll
        for (int s = 0; s < 8; ++s) acc[r][s] = 0.f;

#pragma unroll 8
    for (int c = 0; c < 64; ++c) {
        float4 a0 = *(const float4*)&As[c][ty * 8];
        float4 a1 = *(const float4*)&As[c][ty * 8 + 4];
        float4 b0 = *(const float4*)&Bs[c][tx * 8];
        float4 b1 = *(const float4*)&Bs[c][tx * 8 + 4];
        float av[8] = {a0.x, a0.y, a0.z, a0.w, a1.x, a1.y, a1.z, a1.w};
        float bv[8] = {b0.x, b0.y, b0.z, b0.w, b1.x, b1.y, b1.z, b1.w};
#pragma unroll
        for (int r = 0; r < 8; ++r)
#pragma unroll
            for (int s = 0; s < 8; ++s)
                acc[r][s] = __fmaf_rn(av[r], bv[s], acc[r][s]);
    }

    float sqi[8], sqj[8];
#pragma unroll
    for (int r = 0; r < 8; ++r) sqi[r] = g_sq[b * NN + i0 + ty * 8 + r];
#pragma unroll
    for (int s = 0; s < 8; ++s) sqj[s] = g_sq[b * NN + j0 + tx * 8 + s];

#pragma unroll
    for (int r = 0; r < 8; ++r) {
#pragma unroll
        for (int s = 0; s < 8; ++s)
            acc[r][s] = __fsub_rn(__fadd_rn(sqi[r], sqj[s]), 2.f * acc[r][s]);
        float* dr = g_dist + ((size_t)b * NN + i0 + ty * 8 + r) * NN + j0 + tx * 8;
        float4 o0, o1;
        o0.x = acc[r][0]; o0.y = acc[r][1]; o0.z = acc[r][2]; o0.w = acc[r][3];
        o1.x = acc[r][4]; o1.y = acc[r][5]; o1.z = acc[r][6]; o1.w = acc[r][7];
        *(float4*)dr = o0;
        *(float4*)(dr + 4) = o1;
    }

    if (ti == tj) return;

    __syncthreads();
#pragma unroll
    for (int r = 0; r < 8; ++r)
#pragma unroll
        for (int s = 0; s < 8; ++s)
            Ts[tx * 8 + s][ty * 8 + r] = acc[r][s];
    __syncthreads();
    {
        int row2 = t >> 1;
        int half2 = (t & 1) * 64;
        float* dr = g_dist + ((size_t)b * NN + j0 + row2) * NN + i0 + half2;
#pragma unroll
        for (int u = 0; u < 16; ++u) {
            int k = half2 + 4 * u;
            float4 w;
            w.x = Ts[row2][k];     w.y = Ts[row2][k + 1];
            w.z = Ts[row2][k + 2]; w.w = Ts[row2][k + 3];
            *(float4*)(dr + 4 * u) = w;
        }
    }
}

// ---------------- 5) top-20: f32 value rounds + u32 j tie-break --------------
// Extraction order identical to (value asc, j asc) lexicographic — same as the
// u64-key version, but with 1-instr FMNMX/IMNMX + 32-bit shfl per step.
__global__ __launch_bounds__(256) void topk_k() {
    int row = blockIdx.x;                 // b*N + i
    int i = row & (NN - 1);
    int t = threadIdx.x;
    int lane = t & 31, warp = t >> 5;
    const float* d = g_dist + (size_t)row * NN;

    float key[8];
#pragma unroll
    for (int q = 0; q < 8; ++q) {
        int j = t + 256 * q;
        float f = d[j];
        key[q] = (j == i) ? F32_INF : f;
    }

    __shared__ float    cv[8][KK];
    __shared__ unsigned cj[8][KK];

    // Phase 1: each warp extracts its top-20 of its 256 values
    for (int r = 0; r < KK; ++r) {
        float m = key[0];
#pragma unroll
        for (int q = 1; q < 8; ++q) m = fminf(m, key[q]);
#pragma unroll
        for (int off = 16; off; off >>= 1)
            m = fminf(m, __shfl_down_sync(0xFFFFFFFFu, m, off));
        m = __shfl_sync(0xFFFFFFFFu, m, 0);

        unsigned jc = 0xFFFFFFFFu;
#pragma unroll
        for (int q = 7; q >= 0; --q)
            if (key[q] == m) jc = (unsigned)(t + 256 * q);
#pragma unroll
        for (int off = 16; off; off >>= 1) {
            unsigned o = __shfl_down_sync(0xFFFFFFFFu, jc, off);
            jc = (o < jc) ? o : jc;
        }
        jc = __shfl_sync(0xFFFFFFFFu, jc, 0);

        if (lane == 0) { cv[warp][r] = m; cj[warp][r] = jc; }
#pragma unroll
        for (int q = 0; q < 8; ++q)
            if (jc == (unsigned)(t + 256 * q)) key[q] = F32_INF;
    }
    __syncthreads();

    // Phase 2: warp 0 merges the 160 candidates
    if (warp == 0) {
        float    v2[5];
        unsigned j2[5];
#pragma unroll
        for (int u = 0; u < 5; ++u) {
            int idx = lane + u * 32;            // < 160
            v2[u] = cv[idx / KK][idx % KK];
            j2[u] = cj[idx / KK][idx % KK];
        }
        for (int r = 0; r < KK; ++r) {
            float m = v2[0];
#pragma unroll
            for (int u = 1; u < 5; ++u) m = fminf(m, v2[u]);
#pragma unroll
            for (int off = 16; off; off >>= 1)
                m = fminf(m, __shfl_down_sync(0xFFFFFFFFu, m, off));
            m = __shfl_sync(0xFFFFFFFFu, m, 0);

            unsigned jc = 0xFFFFFFFFu;
#pragma unroll
            for (int u = 4; u >= 0; --u)
                if (v2[u] == m) jc = j2[u];
#pragma unroll
            for (int off = 16; off; off >>= 1) {
                unsigned o = __shfl_down_sync(0xFFFFFFFFu, jc, off);
                jc = (o < jc) ? o : jc;
            }
            jc = __shfl_sync(0xFFFFFFFFu, jc, 0);

            if (lane == 0) g_idx[row * KK + r] = (int)jc;
#pragma unroll
            for (int u = 0; u < 5; ++u)
                if (v2[u] == m && j2[u] == jc) v2[u] = F32_INF;
        }
    }
}

// ---------------- 6) edge conv with packed FFMA2 -----------------------------
// fma.rn.f32x2 per lane == scalar FFMA rn; per-output chain (c ascending)
// unchanged -> bit-identical y, half the FMA-pipe ops.
__global__ __launch_bounds__(256) void conv_k(const float* __restrict__ bias) {
    __shared__ float As[64][68];   // [p][c] gathered features
    __shared__ float Ws[64][64];   // [c][o]

    int n0 = blockIdx.x * 64;
    int b = blockIdx.y;
    int t = threadIdx.x;
    int o4 = t & 15;      // output group (4 outs)
    int p4 = t >> 4;      // point group (4 points)
    int lp = t >> 2;      // gather: point
    int lq = t & 3;       // gather: quarter of the 64-ch row

    unsigned long long accp[4][2];   // [pp][oo-pair]
    {
        float b0 = bias[o4 * 4 + 0], b1 = bias[o4 * 4 + 1];
        float b2 = bias[o4 * 4 + 2], b3 = bias[o4 * 4 + 3];
        unsigned long long p01, p23;
        PK2(p01, b0, b1);
        PK2(p23, b2, b3);
#pragma unroll
        for (int pp = 0; pp < 4; ++pp) { accp[pp][0] = p01; accp[pp][1] = p23; }
    }

    for (int j = 0; j <= KK; ++j) {
        const float4* wsrc = (const float4*)(g_wc + j * CC * OUTC);
#pragma unroll
        for (int u = 0; u < 4; ++u)
            ((float4*)&Ws[0][0])[t + 256 * u] = wsrc[t + 256 * u];

        int g = (j < KK) ? g_idx[((b << 11) + n0 + lp) * KK + j] : (n0 + lp);
        const float4* src =
            (const float4*)(g_xt + ((size_t)(b << 11) + g) * CC) + lq * 4;
#pragma unroll
        for (int u = 0; u < 4; ++u) {
            float4 v = src[u];
            *(float4*)&As[lp][lq * 16 + u * 4] = v;
        }
        __syncthreads();

#pragma unroll 8
        for (int c = 0; c < 64; ++c) {
            float4 w4 = *(const float4*)&Ws[c][o4 * 4];
            unsigned long long w01, w23;
            PK2(w01, w4.x, w4.y);
            PK2(w23, w4.z, w4.w);
#pragma unroll
            for (int pp = 0; pp < 4; ++pp) {
                float a = As[p4 * 4 + pp][c];
                unsigned long long a2;
                PK2(a2, a, a);
                FMA2(accp[pp][0], a2, w01);
                FMA2(accp[pp][1], a2, w23);
            }
        }
        __syncthreads();
    }

#pragma unroll
    for (int pp = 0; pp < 4; ++pp) {
        float r0, r1, r2, r3;
        UPK2(r0, r1, accp[pp][0]);
        UPK2(r2, r3, accp[pp][1]);
        size_t base = (size_t)b * OUTC * NN + n0 + p4 * 4 + pp;
        g_y[base + (size_t)(o4 * 4 + 0) * NN] = r0;
        g_y[base + (size_t)(o4 * 4 + 1) * NN] = r1;
        g_y[base + (size_t)(o4 * 4 + 2) * NN] = r2;
        g_y[base + (size_t)(o4 * 4 + 3) * NN] = r3;
    }
}

// ---------------- 7) BN stats per output channel -----------------------------
__global__ void stats_k(const float* __restrict__ gamma,
                        const float* __restrict__ beta) {
    int o = blockIdx.x;
    int t = threadIdx.x;
    float s = 0.f, ss = 0.f;
    for (int b = 0; b < BB; ++b) {
        const float* p = g_y + (size_t)b * OUTC * NN + (size_t)o * NN;
        for (int n = t; n < NN; n += 256) {
            float v = p[n];
            s += v;
            ss += v * v;
        }
    }
    __shared__ float rs[256], rs2[256];
    rs[t] = s; rs2[t] = ss;
    __syncthreads();
    for (int off = 128; off; off >>= 1) {
        if (t < off) { rs[t] += rs[t + off]; rs2[t] += rs2[t + off]; }
        __syncthreads();
    }
    if (t == 0) {
        float inv = 1.f / (float)(BB * NN);
        float mean = rs[0] * inv;
        float var = rs2[0] * inv - mean * mean;
        if (var < 0.f) var = 0.f;
        float sc = gamma[o] * rsqrtf(var + EPS);
        g_scale[o] = sc;
        g_shift[o] = beta[o] - mean * sc;
    }
}

// ---------------- 8) normalize + leaky relu ----------------------------------
__global__ void final_k(float* __restrict__ out) {
    int i4 = blockIdx.x * 256 + threadIdx.x;   // float4 index
    int e = i4 * 4;
    int o = (e >> 11) & 63;
    float sc = g_scale[o], sh = g_shift[o];
    float4 v = ((const float4*)g_y)[i4];
    float4 r;
    r.x = v.x * sc + sh; r.x = (r.x >= 0.f) ? r.x : NEG_SLOPE * r.x;
    r.y = v.y * sc + sh; r.y = (r.y >= 0.f) ? r.y : NEG_SLOPE * r.y;
    r.z = v.z * sc + sh; r.z = (r.z >= 0.f) ? r.z : NEG_SLOPE * r.z;
    r.w = v.w * sc + sh; r.w = (r.w >= 0.f) ? r.w : NEG_SLOPE * r.w;
    ((float4*)out)[i4] = r;
}

// ---------------- launch -----------------------------------------------------
extern "C" void kernel_launch(void* const* d_in, const int* in_sizes, int n_in,
                              void* d_out, int out_size) {
    const float* x     = (const float*)d_in[0];
    const float* w     = (const float*)d_in[1];
    const float* bias  = (const float*)d_in[2];
    const float* gamma = (const float*)d_in[3];
    const float* beta  = (const float*)d_in[4];
    float* out = (float*)d_out;

    transpose_k<<<dim3(NN / 32, CC / 32, BB), dim3(32, 8)>>>(x);
    sq_k<<<(BB * NN + 255) / 256, 256>>>();
    wcomb_k<<<((KK + 1) * CC * OUTC + 255) / 256, 256>>>(w);

    const int dist_smem = 2 * 64 * 132 * sizeof(float);   // 67584 B (Ts overlays)
    cudaFuncSetAttribute(dist_k, cudaFuncAttributeMaxDynamicSharedMemorySize,
                         dist_smem);
    dist_k<<<dim3(136, 1, BB), 256, dist_smem>>>();

    topk_k<<<BB * NN, 256>>>();
    conv_k<<<dim3(NN / 64, BB), 256>>>(bias);
    stats_k<<<OUTC, 256>>>(gamma, beta);
    final_k<<<(BB * OUTC * NN) / (4 * 256), 256>>>(out);
}